// round 8
// baseline (speedup 1.0000x reference)
#include <cuda_runtime.h>
#include <cuda_bf16.h>

// diag-embed: out[i, j, k] = (j == k) ? x[i, j] : 0
// x: [8192, 176] fp32, out: [8192, 176, 176] fp32 (~1.015 GB of stores).
//
// R8: two-pass split to isolate the store stream from all index/load work.
//   Pass 1: pure zero-fill. Warp-tile = 256 consecutive float4 chunks; lane
//           writes base+lane+32k (k=0..7). n4 % 256 == 0 -> no tail. ~11
//           issued instrs per 4KB warp-tile: the cleanest write stream
//           expressible on this chip.
//   Pass 2: diagonal scatter. 1.44M 4B stores (one per output row) over the
//           zeroed buffer (~46 MB of dirty sectors, ~10 us), serialized
//           after the fill by stream order.

#define D_MODEL 176u
#define CPR 44u
#define BLOCKS 1184u       // 148 SMs * 8 blocks
#define THREADS 256u

__global__ __launch_bounds__(THREADS) void fill_zero_kernel(
        float4* __restrict__ out, unsigned ntiles) {
    // warp-tile = 256 consecutive chunks (4 KB)
    const unsigned lane  = threadIdx.x & 31u;
    const unsigned warp  = (blockIdx.x * THREADS + threadIdx.x) >> 5;
    const unsigned nwarp = (BLOCKS * THREADS) >> 5;   // 9472 warps

    const float4 z = make_float4(0.f, 0.f, 0.f, 0.f);

    for (unsigned t = warp; t < ntiles; t += nwarp) {
        float4* p = out + (size_t)t * 256u + lane;
        #pragma unroll
        for (int k = 0; k < 8; ++k)
            __stcs(p + 32 * k, z);                    // all coalesced STG.128
    }
}

__global__ __launch_bounds__(THREADS) void diag_scatter_kernel(
        const float* __restrict__ x,
        float* __restrict__ out, unsigned n_rows) {
    const unsigned stride = BLOCKS * THREADS;
    unsigned rowg = blockIdx.x * THREADS + threadIdx.x;

    #pragma unroll 4
    for (; rowg < n_rows; rowg += stride) {
        unsigned row = rowg % D_MODEL;                // diag position
        float xv = __ldg(x + rowg);                   // coalesced read
        __stcs(out + (size_t)rowg * D_MODEL + row, xv);
    }
}

extern "C" void kernel_launch(void* const* d_in, const int* in_sizes, int n_in,
                              void* d_out, int out_size) {
    const float* x = (const float*)d_in[0];

    unsigned n4     = (unsigned)(out_size / 4);       // 63,438,848 chunks
    unsigned ntiles = n4 / 256u;                      // exact: 247,808 tiles
    unsigned n_rows = (unsigned)(out_size / (int)D_MODEL);   // 1,441,792

    fill_zero_kernel<<<BLOCKS, THREADS>>>((float4*)d_out, ntiles);
    diag_scatter_kernel<<<BLOCKS, THREADS>>>(x, (float*)d_out, n_rows);
}

// round 9
// speedup vs baseline: 1.3957x; 1.3957x over previous
#include <cuda_runtime.h>
#include <cuda_bf16.h>

// diag-embed: out[i, j, k] = (j == k) ? x[i, j] : 0
// x: [8192, 176] fp32, out: [8192, 176, 176] fp32 (~1.015 GB of stores).
//
// R9: controlled A/B of store cache policy on the proven R4 body.
//   kernel A (__stcs, evict-first)  -> first  half of output
//   kernel B (__stwt, write-through, no L2 write-allocate) -> second half
// Identical body/grid otherwise (1184 x 256, branchless selects, one L2-hot
// LDG, unroll 8). ncu reports each kernel separately -> decisive comparison.

#define D_MODEL 176u
#define CPR 44u            // float4 chunks per output row
#define BLOCKS 1184u       // 148 SMs * 8 blocks
#define THREADS 256u

__device__ __forceinline__ float4 chunk_val(const float* __restrict__ x,
                                            unsigned g) {
    unsigned rowg = g / CPR;                 // 32-bit magic div
    unsigned q    = g - rowg * CPR;          // chunk within row
    unsigned row  = rowg % D_MODEL;          // diag position in row

    float xv = __ldg(x + rowg);              // L1/L2-hot (x = 5.8 MB)

    unsigned c0 = q * 4u;
    float4 v;
    v.x = (c0      == row) ? xv : 0.f;
    v.y = (c0 + 1u == row) ? xv : 0.f;
    v.z = (c0 + 2u == row) ? xv : 0.f;
    v.w = (c0 + 3u == row) ? xv : 0.f;
    return v;
}

__global__ __launch_bounds__(THREADS) void diag_embed_stcs(
        const float* __restrict__ x, float4* __restrict__ out,
        unsigned base, unsigned count) {
    const unsigned stride = BLOCKS * THREADS;
    unsigned i = blockIdx.x * THREADS + threadIdx.x;
    #pragma unroll 8
    for (; i < count; i += stride) {
        unsigned g = base + i;
        __stcs(out + g, chunk_val(x, g));
    }
}

__global__ __launch_bounds__(THREADS) void diag_embed_stwt(
        const float* __restrict__ x, float4* __restrict__ out,
        unsigned base, unsigned count) {
    const unsigned stride = BLOCKS * THREADS;
    unsigned i = blockIdx.x * THREADS + threadIdx.x;
    #pragma unroll 8
    for (; i < count; i += stride) {
        unsigned g = base + i;
        __stwt(out + g, chunk_val(x, g));
    }
}

extern "C" void kernel_launch(void* const* d_in, const int* in_sizes, int n_in,
                              void* d_out, int out_size) {
    const float* x = (const float*)d_in[0];
    float4* out = (float4*)d_out;

    unsigned n4   = (unsigned)(out_size / 4);   // 63,438,848 chunks
    unsigned half = n4 / 2u;                    // exact split (n4 even)

    diag_embed_stcs<<<BLOCKS, THREADS>>>(x, out, 0u,   half);
    diag_embed_stwt<<<BLOCKS, THREADS>>>(x, out, half, n4 - half);
}

// round 10
// speedup vs baseline: 1.4386x; 1.0307x over previous
#include <cuda_runtime.h>
#include <cuda_bf16.h>

// diag-embed: out[i, j, k] = (j == k) ? x[i, j] : 0
// x: [8192, 176] fp32, out: [8192, 176, 176] fp32 (~1.015 GB of stores).
//
// FINAL (= R4 champion): pure HBM-write-bound at the measured ~6.4 TB/s
// pure-write ceiling of this part. Shape that reaches it:
//   - 1184 blocks x 256 threads = exactly 8 blocks/SM, ~97% occupancy,
//     fine-grained whole-grid interleaved store stream (beats slab/tile
//     layouts: R7, R8)
//   - branchless diagonal insertion: unconditional L2-hot LDG + 4 selects
//     (no BSSY/BSYNC divergence)
//   - 32-bit magic div/mod index math (cheaper indexing variants R6/R8
//     showed zero gain: issue was never binding at 28%)
//   - __stcs streaming stores (A/B vs __stwt in R9: identical rate)
//   - unroll 8 for independent STG.128s in flight

#define D_MODEL 176u
#define CPR 44u            // float4 chunks per output row
#define BLOCKS 1184u       // 148 SMs * 8 blocks -> perfectly balanced
#define THREADS 256u

__global__ __launch_bounds__(THREADS) void diag_embed_kernel(
        const float* __restrict__ x,
        float4* __restrict__ out,
        unsigned n4) {
    const unsigned stride = BLOCKS * THREADS;
    unsigned g = blockIdx.x * THREADS + threadIdx.x;

    #pragma unroll 8
    for (; g < n4; g += stride) {
        unsigned rowg = g / CPR;                 // 32-bit magic div
        unsigned q    = g - rowg * CPR;          // chunk within row
        unsigned row  = rowg % D_MODEL;          // diag position in row

        // Unconditional: warp's chunks span <=2 rows -> 1-2 L2-hot sectors.
        float xv = __ldg(x + rowg);

        unsigned c0 = q * 4u;                    // column of v.x
        float4 v;
        v.x = (c0        == row) ? xv : 0.f;
        v.y = (c0 + 1u   == row) ? xv : 0.f;
        v.z = (c0 + 2u   == row) ? xv : 0.f;
        v.w = (c0 + 3u   == row) ? xv : 0.f;

        __stcs(out + g, v);                      // streaming store
    }
}

extern "C" void kernel_launch(void* const* d_in, const int* in_sizes, int n_in,
                              void* d_out, int out_size) {
    const float* x = (const float*)d_in[0];
    float4* out = (float4*)d_out;

    unsigned n4 = (unsigned)(out_size / 4);      // 63,438,848 float4 chunks

    diag_embed_kernel<<<BLOCKS, THREADS>>>(x, out, n4);
}